// round 5
// baseline (speedup 1.0000x reference)
#include <cuda_runtime.h>
#include <cuda_fp16.h>
#include <cuda_bf16.h>
#include <cstdint>

#define MAX_NODES 100000
#define MAX_EDGES 1600000
#define D 64
#define MAX_PARTS 512

// ---------------- scratch (device globals) ----------------
__device__ int    g_counts[MAX_NODES + 1];
__device__ int    g_cursor[MAX_NODES + 1];
__device__ int    g_offsets[MAX_NODES + 1];
__device__ float  g_invdeg[MAX_NODES];
__device__ int    g_nbr[MAX_EDGES];
__device__ int    g_part[MAX_PARTS];
__device__ int    g_partoff[MAX_PARTS];
__device__ __half g_xh[(size_t)MAX_NODES * D];
__device__ float  g_agg[(size_t)MAX_NODES * D];
__device__ float  g_s1[(size_t)MAX_NODES * D];
__device__ float  g_h1[(size_t)MAX_NODES * D];
__device__ float4 g_z[MAX_NODES];
__device__ float4 g_s[MAX_NODES];

// ---------------- f32x2 packed helpers (sm_103a) ----------------
__device__ __forceinline__ unsigned long long pk2(float lo, float hi) {
    unsigned long long r;
    asm("mov.b64 %0, {%1, %2};" : "=l"(r) : "f"(lo), "f"(hi));
    return r;
}
__device__ __forceinline__ void fma2(unsigned long long& acc,
                                     unsigned long long a, unsigned long long b) {
    asm("fma.rn.f32x2 %0, %1, %2, %0;" : "+l"(acc) : "l"(a), "l"(b));
}
__device__ __forceinline__ float2 upk2(unsigned long long v) {
    float2 f;
    asm("mov.b64 {%0, %1}, %2;" : "=f"(f.x), "=f"(f.y) : "l"(v));
    return f;
}

// ---------------- fp16 convert ----------------
__global__ void x2h_kernel(const float* __restrict__ x, int n_elem) {
    int i = (blockIdx.x * blockDim.x + threadIdx.x) * 4;
    if (i + 4 <= n_elem) {
        float4 v = *(const float4*)(x + i);
        __half2 a = __floats2half2_rn(v.x, v.y);
        __half2 b = __floats2half2_rn(v.z, v.w);
        uint2 o;
        o.x = *(unsigned int*)&a;
        o.y = *(unsigned int*)&b;
        *(uint2*)(g_xh + i) = o;
    } else {
        for (int j = i; j < n_elem; ++j) g_xh[j] = __float2half(x[j]);
    }
}

// ---------------- CSR build ----------------
__global__ void zero_counts_kernel(int n_nodes) {
    int i = blockIdx.x * blockDim.x + threadIdx.x;
    if (i < n_nodes) g_counts[i] = 0;
}

// 8 edges per thread, independent RED chains
__global__ void hist_kernel(const int* __restrict__ edge_dst, int n_edges) {
    int i8 = (blockIdx.x * blockDim.x + threadIdx.x) * 8;
    if (i8 + 8 <= n_edges) {
        int4 a = *(const int4*)(edge_dst + i8);
        int4 b = *(const int4*)(edge_dst + i8 + 4);
        atomicAdd(&g_counts[a.x], 1);
        atomicAdd(&g_counts[a.y], 1);
        atomicAdd(&g_counts[a.z], 1);
        atomicAdd(&g_counts[a.w], 1);
        atomicAdd(&g_counts[b.x], 1);
        atomicAdd(&g_counts[b.y], 1);
        atomicAdd(&g_counts[b.z], 1);
        atomicAdd(&g_counts[b.w], 1);
    } else {
        for (int i = i8; i < n_edges; ++i) atomicAdd(&g_counts[edge_dst[i]], 1);
    }
}

__global__ __launch_bounds__(256) void scanA_kernel(int n_nodes) {
    __shared__ int wsum[8];
    int i = blockIdx.x * 256 + threadIdx.x;
    int c = (i < n_nodes) ? g_counts[i] : 0;
    int lane = threadIdx.x & 31, wid = threadIdx.x >> 5;
    int v = c;
    #pragma unroll
    for (int o = 1; o < 32; o <<= 1) {
        int u = __shfl_up_sync(0xffffffffu, v, o);
        if (lane >= o) v += u;
    }
    if (lane == 31) wsum[wid] = v;
    __syncthreads();
    if (wid == 0) {
        int w = (lane < 8) ? wsum[lane] : 0;
        #pragma unroll
        for (int o = 1; o < 8; o <<= 1) {
            int u = __shfl_up_sync(0xffffffffu, w, o);
            if (lane >= o) w += u;
        }
        if (lane < 8) wsum[lane] = w;
    }
    __syncthreads();
    int base = (wid > 0) ? wsum[wid - 1] : 0;
    int incl = v + base;
    if (i < n_nodes) g_offsets[i] = incl - c;
    if (threadIdx.x == 255) g_part[blockIdx.x] = incl;
}

__global__ __launch_bounds__(512) void scanB_kernel(int np) {
    __shared__ int wtot[16];
    int t = threadIdx.x;
    int lane = t & 31, wid = t >> 5;
    int orig = (t < np) ? g_part[t] : 0;
    int v = orig;
    #pragma unroll
    for (int o = 1; o < 32; o <<= 1) {
        int u = __shfl_up_sync(0xffffffffu, v, o);
        if (lane >= o) v += u;
    }
    if (lane == 31) wtot[wid] = v;
    __syncthreads();
    if (wid == 0) {
        int w = (lane < 16) ? wtot[lane] : 0;
        #pragma unroll
        for (int o = 1; o < 16; o <<= 1) {
            int u = __shfl_up_sync(0xffffffffu, w, o);
            if (lane >= o) w += u;
        }
        if (lane < 16) wtot[lane] = w;
    }
    __syncthreads();
    int base = (wid > 0) ? wtot[wid - 1] : 0;
    g_partoff[t] = v + base - orig;
}

__global__ void scanC_kernel(int n_nodes, int n_edges) {
    int i = blockIdx.x * blockDim.x + threadIdx.x;
    if (i < n_nodes) {
        int off = g_offsets[i] + g_partoff[i >> 8];
        g_offsets[i] = off;
        g_cursor[i]  = off;
        g_invdeg[i]  = 1.0f / fmaxf((float)g_counts[i], 1.0f);
    }
    if (i == 0) g_offsets[n_nodes] = n_edges;
}

// 8 edges per thread
__global__ void scatter_kernel(const int* __restrict__ edge_src,
                               const int* __restrict__ edge_dst, int n_edges) {
    int i8 = (blockIdx.x * blockDim.x + threadIdx.x) * 8;
    if (i8 + 8 <= n_edges) {
        int4 d0 = *(const int4*)(edge_dst + i8);
        int4 d1 = *(const int4*)(edge_dst + i8 + 4);
        int4 s0 = *(const int4*)(edge_src + i8);
        int4 s1 = *(const int4*)(edge_src + i8 + 4);
        int p0 = atomicAdd(&g_cursor[d0.x], 1);
        int p1 = atomicAdd(&g_cursor[d0.y], 1);
        int p2 = atomicAdd(&g_cursor[d0.z], 1);
        int p3 = atomicAdd(&g_cursor[d0.w], 1);
        int p4 = atomicAdd(&g_cursor[d1.x], 1);
        int p5 = atomicAdd(&g_cursor[d1.y], 1);
        int p6 = atomicAdd(&g_cursor[d1.z], 1);
        int p7 = atomicAdd(&g_cursor[d1.w], 1);
        g_nbr[p0] = s0.x; g_nbr[p1] = s0.y; g_nbr[p2] = s0.z; g_nbr[p3] = s0.w;
        g_nbr[p4] = s1.x; g_nbr[p5] = s1.y; g_nbr[p6] = s1.z; g_nbr[p7] = s1.w;
    } else {
        for (int i = i8; i < n_edges; ++i) {
            int p = atomicAdd(&g_cursor[edge_dst[i]], 1);
            g_nbr[p] = edge_src[i];
        }
    }
}

// ---------------- layer-1 aggregation: warp/node, no shfl in loop ----------------
// 4 groups of 8 lanes; each group walks its own e-strided neighbor list and
// keeps 2 row-loads in flight. Index loads are direct (8-lane broadcast).
__global__ __launch_bounds__(256) void agg1_kernel(int n_nodes) {
    int gw   = (blockIdx.x * blockDim.x + threadIdx.x) >> 5;
    int lane = threadIdx.x & 31;
    if (gw >= n_nodes) return;
    int beg = g_offsets[gw];
    int end = g_offsets[gw + 1];
    int q  = lane >> 3;
    int l8 = lane & 7;
    float acc[8];
    #pragma unroll
    for (int t = 0; t < 8; ++t) acc[t] = 0.f;

    int e = beg + q;
    for (; e + 4 < end; e += 8) {
        int s0 = __ldg(&g_nbr[e]);
        int s1 = __ldg(&g_nbr[e + 4]);
        uint4 p0 = *(const uint4*)(g_xh + (size_t)s0 * D + l8 * 8);
        uint4 p1 = *(const uint4*)(g_xh + (size_t)s1 * D + l8 * 8);
        const __half2* h0 = (const __half2*)&p0;
        const __half2* h1 = (const __half2*)&p1;
        #pragma unroll
        for (int t = 0; t < 4; ++t) {
            float2 f0 = __half22float2(h0[t]);
            float2 f1 = __half22float2(h1[t]);
            acc[2 * t]     += f0.x + f1.x;
            acc[2 * t + 1] += f0.y + f1.y;
        }
    }
    if (e < end) {
        int s0 = __ldg(&g_nbr[e]);
        uint4 p0 = *(const uint4*)(g_xh + (size_t)s0 * D + l8 * 8);
        const __half2* h0 = (const __half2*)&p0;
        #pragma unroll
        for (int t = 0; t < 4; ++t) {
            float2 f0 = __half22float2(h0[t]);
            acc[2 * t]     += f0.x;
            acc[2 * t + 1] += f0.y;
        }
    }
    // reduce across the 4 q-groups (columns identical per group)
    #pragma unroll
    for (int o = 8; o <= 16; o <<= 1) {
        #pragma unroll
        for (int t = 0; t < 8; ++t) acc[t] += __shfl_xor_sync(0xffffffffu, acc[t], o);
    }
    if (q == 0) {
        float inv = g_invdeg[gw];
        float4 o1 = make_float4(acc[0] * inv, acc[1] * inv, acc[2] * inv, acc[3] * inv);
        float4 o2 = make_float4(acc[4] * inv, acc[5] * inv, acc[6] * inv, acc[7] * inv);
        *(float4*)(g_agg + (size_t)gw * D + l8 * 8)     = o1;
        *(float4*)(g_agg + (size_t)gw * D + l8 * 8 + 4) = o2;
    }
}

// ---------------- dense 64x64 GEMM: k-blocked float4 LDS + f32x2 FMA ------------
// MODE 0: g_s1 = X@W + bias
// MODE 1: g_h1 = tanh(g_s1 + g_agg@W)
template <int MODE>
__global__ __launch_bounds__(256) void gemm_kernel(const float* __restrict__ X,
                                                   const float* __restrict__ W,
                                                   const float* __restrict__ bias,
                                                   int n_nodes) {
    __shared__ float Ts[128][68];   // row stride 68 floats (16B-aligned, padded)
    __shared__ float Wsh[64 * 64];  // [k][n]
    __shared__ float bsh[64];

    const float* __restrict__ src = (MODE == 0) ? X : (const float*)g_agg;

    int tid = threadIdx.x;
    int tx  = tid & 15;   // n: cols tx*4..tx*4+3
    int ty  = tid >> 4;   // m: rows ty*8..ty*8+7
    int m0  = blockIdx.x * 128;

    if (MODE == 0 && tid < 64) bsh[tid] = bias[tid];

    int mrow = tid >> 4;
    int col4 = tid & 15;
    #pragma unroll
    for (int r = 0; r < 8; ++r) {
        int m = r * 16 + mrow;
        float4 v = make_float4(0.f, 0.f, 0.f, 0.f);
        int gm = m0 + m;
        if (gm < n_nodes) v = *(const float4*)(src + (size_t)gm * D + col4 * 4);
        *(float4*)&Ts[m][col4 * 4] = v;
    }
    #pragma unroll
    for (int r = 0; r < 4; ++r) {
        int idx = r * 256 + tid;
        *(float4*)&Wsh[idx * 4] = *(const float4*)(W + (size_t)idx * 4);
    }
    __syncthreads();

    unsigned long long acc2[16];
    #pragma unroll
    for (int i = 0; i < 16; ++i) acc2[i] = 0ULL;

    #pragma unroll
    for (int k0 = 0; k0 < 64; k0 += 4) {
        // per-thread: 4 w float4 loads + 8 a float4 loads = 12 LDS.128 per 4 k
        float4 wv[4];
        #pragma unroll
        for (int kk = 0; kk < 4; ++kk)
            wv[kk] = *(const float4*)&Wsh[(k0 + kk) * 64 + tx * 4];
        unsigned long long w01[4], w23[4];
        #pragma unroll
        for (int kk = 0; kk < 4; ++kk) {
            w01[kk] = pk2(wv[kk].x, wv[kk].y);
            w23[kk] = pk2(wv[kk].z, wv[kk].w);
        }
        #pragma unroll
        for (int i = 0; i < 8; ++i) {
            float4 a4 = *(const float4*)&Ts[ty * 8 + i][k0];
            float av[4] = {a4.x, a4.y, a4.z, a4.w};
            #pragma unroll
            for (int kk = 0; kk < 4; ++kk) {
                unsigned long long aa = pk2(av[kk], av[kk]);
                fma2(acc2[i * 2],     aa, w01[kk]);
                fma2(acc2[i * 2 + 1], aa, w23[kk]);
            }
        }
    }

    #pragma unroll
    for (int i = 0; i < 8; ++i) {
        int m = m0 + ty * 8 + i;
        if (m >= n_nodes) continue;
        float2 r01 = upk2(acc2[i * 2]);
        float2 r23 = upk2(acc2[i * 2 + 1]);
        float4 o;
        if (MODE == 0) {
            o.x = r01.x + bsh[tx * 4 + 0];
            o.y = r01.y + bsh[tx * 4 + 1];
            o.z = r23.x + bsh[tx * 4 + 2];
            o.w = r23.y + bsh[tx * 4 + 3];
            *(float4*)(g_s1 + (size_t)m * D + tx * 4) = o;
        } else {
            float4 s = *(const float4*)(g_s1 + (size_t)m * D + tx * 4);
            o.x = tanhf(r01.x + s.x);
            o.y = tanhf(r01.y + s.y);
            o.z = tanhf(r23.x + s.z);
            o.w = tanhf(r23.y + s.w);
            *(float4*)(g_h1 + (size_t)m * D + tx * 4) = o;
        }
    }
}

// ---------------- layer-2 projections: z = h1@Wn2, s = h1@Ws2 + b2 --------------
__global__ __launch_bounds__(256) void zproj_kernel(const float* __restrict__ Ws2,
                                                    const float* __restrict__ b2,
                                                    const float* __restrict__ Wn2,
                                                    int n_nodes) {
    __shared__ float ws[256], wn[256], bs[4];
    int t = threadIdx.x;
    ws[t] = Ws2[t];
    wn[t] = Wn2[t];
    if (t < 4) bs[t] = b2[t];
    __syncthreads();

    int n = blockIdx.x * blockDim.x + t;
    if (n >= n_nodes) return;

    float s0 = bs[0], s1 = bs[1], s2 = bs[2], s3 = bs[3];
    float z0 = 0.f, z1 = 0.f, z2 = 0.f, z3 = 0.f;
    const float4* hp = (const float4*)(g_h1 + (size_t)n * D);
    #pragma unroll
    for (int q = 0; q < 16; ++q) {
        float4 h = hp[q];
        float hv[4] = {h.x, h.y, h.z, h.w};
        #pragma unroll
        for (int j = 0; j < 4; ++j) {
            int k = q * 4 + j;
            float4 w = *(const float4*)&ws[k * 4];
            float4 v = *(const float4*)&wn[k * 4];
            s0 += hv[j] * w.x; s1 += hv[j] * w.y; s2 += hv[j] * w.z; s3 += hv[j] * w.w;
            z0 += hv[j] * v.x; z1 += hv[j] * v.y; z2 += hv[j] * v.z; z3 += hv[j] * v.w;
        }
    }
    g_s[n] = make_float4(s0, s1, s2, s3);
    g_z[n] = make_float4(z0, z1, z2, z3);
}

// ---------------- layer-2 aggregation over z (4-wide) + finalize ----------------
__global__ __launch_bounds__(256) void agg2_kernel(float* __restrict__ out,
                                                   int n_nodes) {
    int n = blockIdx.x * blockDim.x + threadIdx.x;
    if (n >= n_nodes) return;
    int beg = g_offsets[n];
    int end = g_offsets[n + 1];
    float4 acc = make_float4(0.f, 0.f, 0.f, 0.f);
    int e = beg;
    for (; e + 4 <= end; e += 4) {
        int i0 = g_nbr[e], i1 = g_nbr[e + 1], i2 = g_nbr[e + 2], i3 = g_nbr[e + 3];
        float4 a = g_z[i0], b = g_z[i1], c = g_z[i2], d = g_z[i3];
        acc.x += a.x + b.x + c.x + d.x;
        acc.y += a.y + b.y + c.y + d.y;
        acc.z += a.z + b.z + c.z + d.z;
        acc.w += a.w + b.w + c.w + d.w;
    }
    for (; e < end; ++e) {
        float4 a = g_z[g_nbr[e]];
        acc.x += a.x; acc.y += a.y; acc.z += a.z; acc.w += a.w;
    }
    float inv = g_invdeg[n];
    float4 s = g_s[n];
    float4 o = make_float4(s.x + acc.x * inv, s.y + acc.y * inv,
                           s.z + acc.z * inv, s.w + acc.w * inv);
    *(float4*)(out + (size_t)n * 4) = o;
}

// ---------------- side stream ----------------
namespace {
struct Ctx {
    cudaStream_t s2;
    cudaEvent_t eFork, eJoin;
    Ctx() {
        cudaStreamCreate(&s2);
        cudaEventCreateWithFlags(&eFork, cudaEventDisableTiming);
        cudaEventCreateWithFlags(&eJoin, cudaEventDisableTiming);
    }
};
Ctx g_ctx;
}

// ---------------- launch ----------------
extern "C" void kernel_launch(void* const* d_in, const int* in_sizes, int n_in,
                              void* d_out, int out_size) {
    const float* x    = (const float*)d_in[0];
    const int*   esrc = (const int*)d_in[1];
    const int*   edst = (const int*)d_in[2];
    const float* Ws1  = (const float*)d_in[3];
    const float* b1   = (const float*)d_in[4];
    const float* Wn1  = (const float*)d_in[5];
    const float* Ws2  = (const float*)d_in[6];
    const float* b2   = (const float*)d_in[7];
    const float* Wn2  = (const float*)d_in[8];
    float* out = (float*)d_out;

    int n_nodes = in_sizes[0] / D;
    int n_edges = in_sizes[1];
    int n_elem  = n_nodes * D;
    int np = (n_nodes + 255) / 256;
    int e8_blocks = ((n_edges + 7) / 8 + 255) / 256;
    int gemm_blocks = (n_nodes + 127) / 128;

    // fork: side stream does fp16 convert + self-GEMM while main builds CSR
    cudaEventRecord(g_ctx.eFork, 0);
    cudaStreamWaitEvent(g_ctx.s2, g_ctx.eFork, 0);
    x2h_kernel<<<((n_elem + 3) / 4 + 255) / 256, 256, 0, g_ctx.s2>>>(x, n_elem);
    gemm_kernel<0><<<gemm_blocks, 256, 0, g_ctx.s2>>>(x, Ws1, b1, n_nodes);
    cudaEventRecord(g_ctx.eJoin, g_ctx.s2);

    // main: CSR build (dst -> src)
    zero_counts_kernel<<<(n_nodes + 255) / 256, 256>>>(n_nodes);
    hist_kernel<<<e8_blocks, 256>>>(edst, n_edges);
    scanA_kernel<<<np, 256>>>(n_nodes);
    scanB_kernel<<<1, MAX_PARTS>>>(np);
    scanC_kernel<<<(n_nodes + 255) / 256, 256>>>(n_nodes, n_edges);
    scatter_kernel<<<e8_blocks, 256>>>(esrc, edst, n_edges);

    // join
    cudaStreamWaitEvent(0, g_ctx.eJoin, 0);

    int agg_blocks = (n_nodes * 32 + 255) / 256;
    agg1_kernel<<<agg_blocks, 256>>>(n_nodes);
    gemm_kernel<1><<<gemm_blocks, 256>>>(x, Wn1, b1, n_nodes);

    // layer 2 (project-then-aggregate)
    zproj_kernel<<<(n_nodes + 255) / 256, 256>>>(Ws2, b2, Wn2, n_nodes);
    agg2_kernel<<<(n_nodes + 255) / 256, 256>>>(out, n_nodes);
}

// round 6
// speedup vs baseline: 1.1558x; 1.1558x over previous
#include <cuda_runtime.h>
#include <cuda_fp16.h>
#include <cuda_bf16.h>
#include <cstdint>

#define MAX_NODES 100000
#define MAX_EDGES 1600000
#define D 64
#define MAX_PARTS 512

// ---------------- scratch (device globals) ----------------
__device__ int    g_counts[MAX_NODES + 1];
__device__ int    g_cursor[MAX_NODES + 1];
__device__ int    g_offsets[MAX_NODES + 1];
__device__ float  g_invdeg[MAX_NODES];
__device__ int    g_nbr[MAX_EDGES];
__device__ int    g_part[MAX_PARTS];
__device__ int    g_partoff[MAX_PARTS];
__device__ __half g_xh[(size_t)MAX_NODES * D];
__device__ float  g_s1[(size_t)MAX_NODES * D];
__device__ float4 g_z[MAX_NODES];
__device__ float4 g_s[MAX_NODES];

// ---------------- f32x2 packed helpers (sm_103a) ----------------
__device__ __forceinline__ unsigned long long pk2(float lo, float hi) {
    unsigned long long r;
    asm("mov.b64 %0, {%1, %2};" : "=l"(r) : "f"(lo), "f"(hi));
    return r;
}
__device__ __forceinline__ void fma2(unsigned long long& acc,
                                     unsigned long long a, unsigned long long b) {
    asm("fma.rn.f32x2 %0, %1, %2, %0;" : "+l"(acc) : "l"(a), "l"(b));
}
__device__ __forceinline__ float2 upk2(unsigned long long v) {
    float2 f;
    asm("mov.b64 {%0, %1}, %2;" : "=f"(f.x), "=f"(f.y) : "l"(v));
    return f;
}

// ---------------- CSR build ----------------
__global__ void zero_counts_kernel(int n_nodes) {
    int i = blockIdx.x * blockDim.x + threadIdx.x;
    if (i < n_nodes) g_counts[i] = 0;
}

__global__ void hist_kernel(const int* __restrict__ edge_dst, int n_edges) {
    int i4 = (blockIdx.x * blockDim.x + threadIdx.x) * 4;
    if (i4 + 4 <= n_edges) {
        int4 d = *(const int4*)(edge_dst + i4);
        atomicAdd(&g_counts[d.x], 1);
        atomicAdd(&g_counts[d.y], 1);
        atomicAdd(&g_counts[d.z], 1);
        atomicAdd(&g_counts[d.w], 1);
    } else {
        for (int i = i4; i < n_edges; ++i) atomicAdd(&g_counts[edge_dst[i]], 1);
    }
}

__global__ __launch_bounds__(256) void scanA_kernel(int n_nodes) {
    __shared__ int wsum[8];
    int i = blockIdx.x * 256 + threadIdx.x;
    int c = (i < n_nodes) ? g_counts[i] : 0;
    int lane = threadIdx.x & 31, wid = threadIdx.x >> 5;
    int v = c;
    #pragma unroll
    for (int o = 1; o < 32; o <<= 1) {
        int u = __shfl_up_sync(0xffffffffu, v, o);
        if (lane >= o) v += u;
    }
    if (lane == 31) wsum[wid] = v;
    __syncthreads();
    if (wid == 0) {
        int w = (lane < 8) ? wsum[lane] : 0;
        #pragma unroll
        for (int o = 1; o < 8; o <<= 1) {
            int u = __shfl_up_sync(0xffffffffu, w, o);
            if (lane >= o) w += u;
        }
        if (lane < 8) wsum[lane] = w;
    }
    __syncthreads();
    int base = (wid > 0) ? wsum[wid - 1] : 0;
    int incl = v + base;
    if (i < n_nodes) g_offsets[i] = incl - c;
    if (threadIdx.x == 255) g_part[blockIdx.x] = incl;
}

__global__ __launch_bounds__(512) void scanB_kernel(int np) {
    __shared__ int wtot[16];
    int t = threadIdx.x;
    int lane = t & 31, wid = t >> 5;
    int orig = (t < np) ? g_part[t] : 0;
    int v = orig;
    #pragma unroll
    for (int o = 1; o < 32; o <<= 1) {
        int u = __shfl_up_sync(0xffffffffu, v, o);
        if (lane >= o) v += u;
    }
    if (lane == 31) wtot[wid] = v;
    __syncthreads();
    if (wid == 0) {
        int w = (lane < 16) ? wtot[lane] : 0;
        #pragma unroll
        for (int o = 1; o < 16; o <<= 1) {
            int u = __shfl_up_sync(0xffffffffu, w, o);
            if (lane >= o) w += u;
        }
        if (lane < 16) wtot[lane] = w;
    }
    __syncthreads();
    int base = (wid > 0) ? wtot[wid - 1] : 0;
    g_partoff[t] = v + base - orig;
}

__global__ void scanC_kernel(int n_nodes, int n_edges) {
    int i = blockIdx.x * blockDim.x + threadIdx.x;
    if (i < n_nodes) {
        int off = g_offsets[i] + g_partoff[i >> 8];
        g_offsets[i] = off;
        g_cursor[i]  = off;
        g_invdeg[i]  = 1.0f / fmaxf((float)g_counts[i], 1.0f);
    }
    if (i == 0) g_offsets[n_nodes] = n_edges;
}

__global__ void scatter_kernel(const int* __restrict__ edge_src,
                               const int* __restrict__ edge_dst, int n_edges) {
    int i4 = (blockIdx.x * blockDim.x + threadIdx.x) * 4;
    if (i4 + 4 <= n_edges) {
        int4 d = *(const int4*)(edge_dst + i4);
        int4 sv = *(const int4*)(edge_src + i4);
        int p0 = atomicAdd(&g_cursor[d.x], 1);
        int p1 = atomicAdd(&g_cursor[d.y], 1);
        int p2 = atomicAdd(&g_cursor[d.z], 1);
        int p3 = atomicAdd(&g_cursor[d.w], 1);
        g_nbr[p0] = sv.x; g_nbr[p1] = sv.y; g_nbr[p2] = sv.z; g_nbr[p3] = sv.w;
    } else {
        for (int i = i4; i < n_edges; ++i) {
            int p = atomicAdd(&g_cursor[edge_dst[i]], 1);
            g_nbr[p] = edge_src[i];
        }
    }
}

// ---------------- gemm0: g_s1 = X@Ws1 + b1, also emits fp16 copy of X ----------
__global__ __launch_bounds__(256) void gemm0_kernel(const float* __restrict__ X,
                                                    const float* __restrict__ W,
                                                    const float* __restrict__ bias,
                                                    int n_nodes) {
    __shared__ float Ts[128][68];
    __shared__ float Wsh[64 * 64];
    __shared__ float bsh[64];

    int tid = threadIdx.x;
    int tx  = tid & 15;
    int ty  = tid >> 4;
    int m0  = blockIdx.x * 128;

    if (tid < 64) bsh[tid] = bias[tid];

    int mrow = tid >> 4;
    int col4 = tid & 15;
    #pragma unroll
    for (int r = 0; r < 8; ++r) {
        int m = r * 16 + mrow;
        int gm = m0 + m;
        float4 v = make_float4(0.f, 0.f, 0.f, 0.f);
        if (gm < n_nodes) {
            v = *(const float4*)(X + (size_t)gm * D + col4 * 4);
            // fused fp16 emit (each element written exactly once chip-wide)
            __half2 h0 = __floats2half2_rn(v.x, v.y);
            __half2 h1 = __floats2half2_rn(v.z, v.w);
            uint2 o;
            o.x = *(unsigned int*)&h0;
            o.y = *(unsigned int*)&h1;
            *(uint2*)(g_xh + (size_t)gm * D + col4 * 4) = o;
        }
        *(float4*)&Ts[m][col4 * 4] = v;
    }
    #pragma unroll
    for (int r = 0; r < 4; ++r) {
        int idx = r * 256 + tid;
        *(float4*)&Wsh[idx * 4] = *(const float4*)(W + (size_t)idx * 4);
    }
    __syncthreads();

    unsigned long long acc2[16];
    #pragma unroll
    for (int i = 0; i < 16; ++i) acc2[i] = 0ULL;

    #pragma unroll
    for (int k0 = 0; k0 < 64; k0 += 4) {
        float4 wv[4];
        #pragma unroll
        for (int kk = 0; kk < 4; ++kk)
            wv[kk] = *(const float4*)&Wsh[(k0 + kk) * 64 + tx * 4];
        #pragma unroll
        for (int i = 0; i < 8; ++i) {
            float4 a4 = *(const float4*)&Ts[ty * 8 + i][k0];
            float av[4] = {a4.x, a4.y, a4.z, a4.w};
            #pragma unroll
            for (int kk = 0; kk < 4; ++kk) {
                unsigned long long aa = pk2(av[kk], av[kk]);
                fma2(acc2[i * 2],     aa, pk2(wv[kk].x, wv[kk].y));
                fma2(acc2[i * 2 + 1], aa, pk2(wv[kk].z, wv[kk].w));
            }
        }
    }

    #pragma unroll
    for (int i = 0; i < 8; ++i) {
        int m = m0 + ty * 8 + i;
        if (m >= n_nodes) continue;
        float2 r01 = upk2(acc2[i * 2]);
        float2 r23 = upk2(acc2[i * 2 + 1]);
        float4 o;
        o.x = r01.x + bsh[tx * 4 + 0];
        o.y = r01.y + bsh[tx * 4 + 1];
        o.z = r23.x + bsh[tx * 4 + 2];
        o.w = r23.y + bsh[tx * 4 + 3];
        *(float4*)(g_s1 + (size_t)m * D + tx * 4) = o;
    }
}

// ---------------- fused: agg1 + gemmN + tanh + layer-2 projection ----------------
// Block = 128 nodes.
//  A: gather-mean neighbor fp16 rows -> Ts (fp32, scaled by invdeg)
//  B: acc = Ts @ Wn1 (f32x2), h1 = tanh(g_s1 + acc) -> back into Ts
//  C: s = h1@Ws2+b2, z = h1@Wn2 -> g_s, g_z
__global__ __launch_bounds__(256) void fused_kernel(const float* __restrict__ Wn1,
                                                    const float* __restrict__ Ws2,
                                                    const float* __restrict__ b2,
                                                    const float* __restrict__ Wn2,
                                                    int n_nodes) {
    __shared__ float Ts[128][68];
    __shared__ float Wsh[64 * 64];
    __shared__ float ws2[256], wn2[256], bs2[4];

    int tid = threadIdx.x;
    int m0  = blockIdx.x * 128;

    // weight loads
    #pragma unroll
    for (int r = 0; r < 4; ++r) {
        int idx = r * 256 + tid;
        *(float4*)&Wsh[idx * 4] = *(const float4*)(Wn1 + (size_t)idx * 4);
    }
    ws2[tid] = Ws2[tid];
    wn2[tid] = Wn2[tid];
    if (tid < 4) bs2[tid] = b2[tid];

    // ---- Phase A: gather-mean into Ts ----
    {
        int node = m0 + (tid >> 1);
        int half = tid & 1;           // cols [half*32, half*32+32)
        float acc[32];
        #pragma unroll
        for (int c = 0; c < 32; ++c) acc[c] = 0.f;

        if (node < n_nodes) {
            int beg = g_offsets[node];
            int end = g_offsets[node + 1];
            const __half* base = g_xh + half * 32;
            int e = beg;
            for (; e + 2 <= end; e += 2) {
                int s0 = __ldg(&g_nbr[e]);
                int s1 = __ldg(&g_nbr[e + 1]);
                const uint4* r0 = (const uint4*)(base + (size_t)s0 * D);
                const uint4* r1 = (const uint4*)(base + (size_t)s1 * D);
                uint4 a0 = r0[0], a1 = r0[1], a2 = r0[2], a3 = r0[3];
                uint4 b0 = r1[0], b1 = r1[1], b2_ = r1[2], b3 = r1[3];
                uint4 qa[4] = {a0, a1, a2, a3};
                uint4 qb[4] = {b0, b1, b2_, b3};
                #pragma unroll
                for (int qi = 0; qi < 4; ++qi) {
                    const __half2* ha = (const __half2*)&qa[qi];
                    const __half2* hb = (const __half2*)&qb[qi];
                    #pragma unroll
                    for (int j = 0; j < 4; ++j) {
                        float2 fa = __half22float2(ha[j]);
                        float2 fb = __half22float2(hb[j]);
                        acc[qi * 8 + 2 * j]     += fa.x + fb.x;
                        acc[qi * 8 + 2 * j + 1] += fa.y + fb.y;
                    }
                }
            }
            if (e < end) {
                int s0 = __ldg(&g_nbr[e]);
                const uint4* r0 = (const uint4*)(base + (size_t)s0 * D);
                #pragma unroll
                for (int qi = 0; qi < 4; ++qi) {
                    uint4 q = r0[qi];
                    const __half2* ha = (const __half2*)&q;
                    #pragma unroll
                    for (int j = 0; j < 4; ++j) {
                        float2 fa = __half22float2(ha[j]);
                        acc[qi * 8 + 2 * j]     += fa.x;
                        acc[qi * 8 + 2 * j + 1] += fa.y;
                    }
                }
            }
            float inv = g_invdeg[node];
            #pragma unroll
            for (int c = 0; c < 32; ++c) acc[c] *= inv;
        }
        float* dst = &Ts[tid >> 1][half * 32];
        #pragma unroll
        for (int c = 0; c < 32; c += 4)
            *(float4*)&dst[c] = make_float4(acc[c], acc[c + 1], acc[c + 2], acc[c + 3]);
    }
    __syncthreads();

    // ---- Phase B: GEMM + tanh(s1 + .) -> Ts ----
    int tx = tid & 15;
    int ty = tid >> 4;
    unsigned long long acc2[16];
    #pragma unroll
    for (int i = 0; i < 16; ++i) acc2[i] = 0ULL;

    #pragma unroll
    for (int k0 = 0; k0 < 64; k0 += 4) {
        float4 wv[4];
        #pragma unroll
        for (int kk = 0; kk < 4; ++kk)
            wv[kk] = *(const float4*)&Wsh[(k0 + kk) * 64 + tx * 4];
        #pragma unroll
        for (int i = 0; i < 8; ++i) {
            float4 a4 = *(const float4*)&Ts[ty * 8 + i][k0];
            float av[4] = {a4.x, a4.y, a4.z, a4.w};
            #pragma unroll
            for (int kk = 0; kk < 4; ++kk) {
                unsigned long long aa = pk2(av[kk], av[kk]);
                fma2(acc2[i * 2],     aa, pk2(wv[kk].x, wv[kk].y));
                fma2(acc2[i * 2 + 1], aa, pk2(wv[kk].z, wv[kk].w));
            }
        }
    }

    float h1v[8][4];
    #pragma unroll
    for (int i = 0; i < 8; ++i) {
        int m = m0 + ty * 8 + i;
        float2 r01 = upk2(acc2[i * 2]);
        float2 r23 = upk2(acc2[i * 2 + 1]);
        float4 s = make_float4(0.f, 0.f, 0.f, 0.f);
        if (m < n_nodes) s = *(const float4*)(g_s1 + (size_t)m * D + tx * 4);
        h1v[i][0] = tanhf(r01.x + s.x);
        h1v[i][1] = tanhf(r01.y + s.y);
        h1v[i][2] = tanhf(r23.x + s.z);
        h1v[i][3] = tanhf(r23.y + s.w);
    }
    __syncthreads();  // all Ts reads done
    #pragma unroll
    for (int i = 0; i < 8; ++i)
        *(float4*)&Ts[ty * 8 + i][tx * 4] =
            make_float4(h1v[i][0], h1v[i][1], h1v[i][2], h1v[i][3]);
    __syncthreads();

    // ---- Phase C: project to s (self+bias) and z (neigh) ----
    {
        int row  = tid >> 1;
        int half = tid & 1;
        float s0 = 0.f, s1v = 0.f, s2 = 0.f, s3 = 0.f;
        float z0 = 0.f, z1 = 0.f, z2 = 0.f, z3 = 0.f;
        const float* hr = &Ts[row][half * 32];
        #pragma unroll
        for (int k = 0; k < 32; ++k) {
            float h = hr[k];
            int kk = half * 32 + k;
            float4 w = *(const float4*)&ws2[kk * 4];
            float4 v = *(const float4*)&wn2[kk * 4];
            s0 += h * w.x; s1v += h * w.y; s2 += h * w.z; s3 += h * w.w;
            z0 += h * v.x; z1  += h * v.y; z2 += h * v.z; z3 += h * v.w;
        }
        // combine the two halves (lanes t, t^1)
        s0 += __shfl_xor_sync(0xffffffffu, s0, 1);
        s1v += __shfl_xor_sync(0xffffffffu, s1v, 1);
        s2 += __shfl_xor_sync(0xffffffffu, s2, 1);
        s3 += __shfl_xor_sync(0xffffffffu, s3, 1);
        z0 += __shfl_xor_sync(0xffffffffu, z0, 1);
        z1 += __shfl_xor_sync(0xffffffffu, z1, 1);
        z2 += __shfl_xor_sync(0xffffffffu, z2, 1);
        z3 += __shfl_xor_sync(0xffffffffu, z3, 1);
        int m = m0 + row;
        if (half == 0 && m < n_nodes) {
            g_s[m] = make_float4(s0 + bs2[0], s1v + bs2[1], s2 + bs2[2], s3 + bs2[3]);
            g_z[m] = make_float4(z0, z1, z2, z3);
        }
    }
}

// ---------------- layer-2 aggregation over z (4-wide) + finalize ----------------
__global__ __launch_bounds__(256) void agg2_kernel(float* __restrict__ out,
                                                   int n_nodes) {
    int n = blockIdx.x * blockDim.x + threadIdx.x;
    if (n >= n_nodes) return;
    int beg = g_offsets[n];
    int end = g_offsets[n + 1];
    float4 acc = make_float4(0.f, 0.f, 0.f, 0.f);
    int e = beg;
    for (; e + 4 <= end; e += 4) {
        int i0 = g_nbr[e], i1 = g_nbr[e + 1], i2 = g_nbr[e + 2], i3 = g_nbr[e + 3];
        float4 a = g_z[i0], b = g_z[i1], c = g_z[i2], d = g_z[i3];
        acc.x += a.x + b.x + c.x + d.x;
        acc.y += a.y + b.y + c.y + d.y;
        acc.z += a.z + b.z + c.z + d.z;
        acc.w += a.w + b.w + c.w + d.w;
    }
    for (; e < end; ++e) {
        float4 a = g_z[g_nbr[e]];
        acc.x += a.x; acc.y += a.y; acc.z += a.z; acc.w += a.w;
    }
    float inv = g_invdeg[n];
    float4 s = g_s[n];
    float4 o = make_float4(s.x + acc.x * inv, s.y + acc.y * inv,
                           s.z + acc.z * inv, s.w + acc.w * inv);
    *(float4*)(out + (size_t)n * 4) = o;
}

// ---------------- side stream ----------------
namespace {
struct Ctx {
    cudaStream_t s2;
    cudaEvent_t eFork, eJoin;
    Ctx() {
        cudaStreamCreate(&s2);
        cudaEventCreateWithFlags(&eFork, cudaEventDisableTiming);
        cudaEventCreateWithFlags(&eJoin, cudaEventDisableTiming);
    }
};
Ctx g_ctx;
}

// ---------------- launch ----------------
extern "C" void kernel_launch(void* const* d_in, const int* in_sizes, int n_in,
                              void* d_out, int out_size) {
    const float* x    = (const float*)d_in[0];
    const int*   esrc = (const int*)d_in[1];
    const int*   edst = (const int*)d_in[2];
    const float* Ws1  = (const float*)d_in[3];
    const float* b1   = (const float*)d_in[4];
    const float* Wn1  = (const float*)d_in[5];
    const float* Ws2  = (const float*)d_in[6];
    const float* b2   = (const float*)d_in[7];
    const float* Wn2  = (const float*)d_in[8];
    float* out = (float*)d_out;

    int n_nodes = in_sizes[0] / D;
    int n_edges = in_sizes[1];
    int np = (n_nodes + 255) / 256;
    int e4_blocks = ((n_edges + 3) / 4 + 255) / 256;
    int gemm_blocks = (n_nodes + 127) / 128;

    // fork: side stream runs self-GEMM (+fp16 emit) under the CSR build
    cudaEventRecord(g_ctx.eFork, 0);
    cudaStreamWaitEvent(g_ctx.s2, g_ctx.eFork, 0);
    gemm0_kernel<<<gemm_blocks, 256, 0, g_ctx.s2>>>(x, Ws1, b1, n_nodes);
    cudaEventRecord(g_ctx.eJoin, g_ctx.s2);

    // main: CSR build (dst -> src)
    zero_counts_kernel<<<(n_nodes + 255) / 256, 256>>>(n_nodes);
    hist_kernel<<<e4_blocks, 256>>>(edst, n_edges);
    scanA_kernel<<<np, 256>>>(n_nodes);
    scanB_kernel<<<1, MAX_PARTS>>>(np);
    scanC_kernel<<<(n_nodes + 255) / 256, 256>>>(n_nodes, n_edges);
    scatter_kernel<<<e4_blocks, 256>>>(esrc, edst, n_edges);

    // join: fused needs g_xh + g_s1 from stream2
    cudaStreamWaitEvent(0, g_ctx.eJoin, 0);

    fused_kernel<<<gemm_blocks, 256>>>(Wn1, Ws2, b2, Wn2, n_nodes);
    agg2_kernel<<<(n_nodes + 255) / 256, 256>>>(out, n_nodes);
}